// round 11
// baseline (speedup 1.0000x reference)
#include <cuda_runtime.h>
#include <math.h>
#include <stdint.h>

#define LDIM 4096
#define NPTS 2048
#define WPIX 640.0f
#define HPIX 480.0f
#define ROW_BYTES (NPTS * 2 * 4)        // 16384
#define ROW_F4    (ROW_BYTES / 16)      // 1024
#define GRID      512
#define ROWS      (LDIM / GRID)         // 8

__device__ __forceinline__ uint32_t smem_u32(const void* p)
{
    uint32_t a;
    asm("{ .reg .u64 t; cvta.to.shared.u64 t, %1; cvt.u32.u64 %0, t; }"
        : "=r"(a) : "l"(p));
    return a;
}

__device__ __forceinline__ void mbar_wait(uint32_t mbar_a, uint32_t parity)
{
    asm volatile(
        "{\n\t"
        ".reg .pred p;\n\t"
        "WAIT_%=:\n\t"
        "mbarrier.try_wait.parity.acquire.cta.shared::cta.b64 p, [%0], %1, 0x989680;\n\t"
        "@!p bra.uni WAIT_%=;\n\t"
        "}"
        :: "r"(mbar_a), "r"(parity) : "memory");
}

// ---------------------------------------------------------------------------
// Persistent double-buffered pipeline: 512 blocks (single wave), 8 rows each.
// TMA for row r+1 is in flight while row r is computed -> the SM's DRAM
// demand stream never idles (fixes the ~58% duty-cycle cap of one-shot
// blocks). Per-row tail = reduce + atomics only; the 8 eigensolves are
// deferred and run concurrently in threads 0-7 at the end.
// ---------------------------------------------------------------------------
__global__ void __launch_bounds__(128)
fused_kernel(const float* __restrict__ in,
             const float* __restrict__ center,
             const float* __restrict__ alpha_p,
             float* __restrict__ out)
{
    __shared__ alignas(128) float4 tile[2][ROW_F4];   // 2 x 16 KB
    __shared__ uint64_t mbar[2];
    __shared__ float moments[ROWS][5];

    const int b = blockIdx.x;
    const int t = threadIdx.x;

    const float cx = center[0];
    const float cy = center[1];
    const float alpha = alpha_p[0];
    const float invW = 1.0f / WPIX;
    const float invH = 1.0f / HPIX;

    const uint32_t tile_a[2] = { smem_u32(tile[0]), smem_u32(tile[1]) };
    const uint32_t mbar_a[2] = { smem_u32(&mbar[0]), smem_u32(&mbar[1]) };

    const float* base = in + (size_t)b * ROWS * (NPTS * 2);

    if (t == 0) {
        asm volatile("mbarrier.init.shared.b64 [%0], 1;" :: "r"(mbar_a[0]) : "memory");
        asm volatile("mbarrier.init.shared.b64 [%0], 1;" :: "r"(mbar_a[1]) : "memory");
    }
    if (t < ROWS * 5) ((float*)moments)[t] = 0.f;
    __syncthreads();

    // Prologue: kick off row 0 into stage 0.
    if (t == 0) {
        asm volatile("mbarrier.arrive.expect_tx.shared.b64 _, [%0], %1;"
                     :: "r"(mbar_a[0]), "r"((uint32_t)ROW_BYTES) : "memory");
        asm volatile("cp.async.bulk.shared::cta.global.mbarrier::complete_tx::bytes "
                     "[%0], [%1], %2, [%3];"
                     :: "r"(tile_a[0]), "l"(base), "r"((uint32_t)ROW_BYTES),
                        "r"(mbar_a[0]) : "memory");
    }

    uint32_t phase[2] = {0u, 0u};

    for (int r = 0; r < ROWS; r++) {
        const int s = r & 1;

        // All warps have finished reading stage s^1 (row r-1) -> safe to
        // overwrite it with row r+1.
        if (r > 0) __syncthreads();

        if (t == 0 && r + 1 < ROWS) {
            const int s2 = (r + 1) & 1;
            asm volatile("fence.proxy.async.shared::cta;" ::: "memory");
            asm volatile("mbarrier.arrive.expect_tx.shared.b64 _, [%0], %1;"
                         :: "r"(mbar_a[s2]), "r"((uint32_t)ROW_BYTES) : "memory");
            asm volatile("cp.async.bulk.shared::cta.global.mbarrier::complete_tx::bytes "
                         "[%0], [%1], %2, [%3];"
                         :: "r"(tile_a[s2]),
                            "l"(base + (size_t)(r + 1) * (NPTS * 2)),
                            "r"((uint32_t)ROW_BYTES), "r"(mbar_a[s2]) : "memory");
        }

        mbar_wait(mbar_a[s], phase[s]);
        phase[s] ^= 1u;

        float Sxx = 0.f, Sxy = 0.f, Syy = 0.f, Sx = 0.f, Sy = 0.f;

        #pragma unroll
        for (int k = 0; k < 8; k++) {
            float4 v = tile[s][t + k * 128];   // conflict-free LDS.128

            float sx = v.x * invW - cx;
            float sy = v.y * invH - cy;
            float r2 = sx * sx + sy * sy;
            float f  = 1.0f + alpha * r2;
            float ux = f * sx + cx;
            float uy = f * sy + cy;
            Sxx += ux * ux; Sxy += ux * uy; Syy += uy * uy; Sx += ux; Sy += uy;

            sx = v.z * invW - cx;
            sy = v.w * invH - cy;
            r2 = sx * sx + sy * sy;
            f  = 1.0f + alpha * r2;
            ux = f * sx + cx;
            uy = f * sy + cy;
            Sxx += ux * ux; Sxy += ux * uy; Syy += uy * uy; Sx += ux; Sy += uy;
        }

        #pragma unroll
        for (int o = 16; o > 0; o >>= 1) {
            Sxx += __shfl_xor_sync(0xffffffffu, Sxx, o);
            Sxy += __shfl_xor_sync(0xffffffffu, Sxy, o);
            Syy += __shfl_xor_sync(0xffffffffu, Syy, o);
            Sx  += __shfl_xor_sync(0xffffffffu, Sx,  o);
            Sy  += __shfl_xor_sync(0xffffffffu, Sy,  o);
        }

        if ((t & 31) == 0) {
            atomicAdd(&moments[r][0], Sxx);
            atomicAdd(&moments[r][1], Sxy);
            atomicAdd(&moments[r][2], Syy);
            atomicAdd(&moments[r][3], Sx);
            atomicAdd(&moments[r][4], Sy);
        }
    }

    __syncthreads();

    // Deferred solves: 8 rows solved concurrently by threads 0-7.
    if (t < ROWS) {
        const float* sm = moments[t];
        float m00 =  sm[0];
        float m01 =  sm[1];
        float m11 =  sm[2];
        float m02 = -sm[3];
        float m12 = -sm[4];
        float m22 =  (float)NPTS;

        // Newton on det(M - lam I) from lam = 0: monotone convergence for
        // SPD M with well-separated lam_min.
        float lam = 0.0f;
        #pragma unroll
        for (int it = 0; it < 6; it++) {
            float a00 = m00 - lam, a11 = m11 - lam, a22 = m22 - lam;
            float M0 = a11 * a22 - m12 * m12;
            float M1 = a00 * a22 - m02 * m02;
            float M2 = a00 * a11 - m01 * m01;
            float det = a00 * M0
                      - m01 * (m01 * a22 - m12 * m02)
                      + m02 * (m01 * m12 - a11 * m02);
            float dp = M0 + M1 + M2;           // = -p'(lam)
            lam += det / fmaxf(dp, 1e-20f);
        }

        float c00 = m00 - lam, c11 = m11 - lam, c22 = m22 - lam;

        float x0 = m01 * m12 - m02 * c11;
        float y0 = m02 * m01 - c00 * m12;
        float z0 = c00 * c11 - m01 * m01;
        float n0 = x0 * x0 + y0 * y0 + z0 * z0;

        float x1 = m01 * c22 - m02 * m12;
        float y1 = m02 * m02 - c00 * c22;
        float z1 = c00 * m12 - m01 * m02;
        float n1 = x1 * x1 + y1 * y1 + z1 * z1;

        float x2 = c11 * c22 - m12 * m12;
        float y2 = m12 * m02 - m01 * c22;
        float z2 = m01 * m12 - c11 * m02;
        float n2 = x2 * x2 + y2 * y2 + z2 * z2;

        float vx = x0, vy = y0, vz = z0, nbest = n0;
        if (n1 > nbest) { vx = x1; vy = y1; vz = z1; nbest = n1; }
        if (n2 > nbest) { vx = x2; vy = y2; vz = z2; nbest = n2; }

        float vMv = m00 * vx * vx + m11 * vy * vy + m22 * vz * vz
                  + 2.0f * (m01 * vx * vy + m02 * vx * vz + m12 * vy * vz);
        float denom = vx * vx + vy * vy;
        out[b * ROWS + t] = vMv / denom;
    }
}

extern "C" void kernel_launch(void* const* d_in, const int* in_sizes, int n_in,
                              void* d_out, int out_size)
{
    const float* input  = (const float*)d_in[0];
    const float* center = (const float*)d_in[1];
    const float* alpha  = (const float*)d_in[2];
    float* out = (float*)d_out;

    fused_kernel<<<GRID, 128>>>(input, center, alpha, out);
}